// round 5
// baseline (speedup 1.0000x reference)
#include <cuda_runtime.h>
#include <cuda_bf16.h>

#define N_NODES    1000000
#define NUM_GRAPHS 1024

// Scratch (device globals: no allocations allowed)
__device__ float d_agg[N_NODES];      // per-node aggregated sum
__device__ float d_gsum[NUM_GRAPHS];  // per-graph sum of relu(agg)
__device__ float d_gcnt[NUM_GRAPHS];  // per-graph node count
__device__ int   d_is64;              // 1 if indices are int64, 0 if int32

// ---------------------------------------------------------------------------
// Init: zero scratch + detect index dtype (thread 0).
// JAX with x64 disabled silently downcasts int64->int32. If data is int32,
// an int64-reinterpreted word is (lo,hi) with hi ~ U[0,1e6) -> >= 2^32 with
// overwhelming probability. True int64 indices are < 1e6.
// ---------------------------------------------------------------------------
__global__ void init_kernel(const void* __restrict__ edges) {
    int i = blockIdx.x * blockDim.x + threadIdx.x;
    if (i < N_NODES) d_agg[i] = 0.0f;
    if (i < NUM_GRAPHS) { d_gsum[i] = 0.0f; d_gcnt[i] = 0.0f; }
    if (i == 0) {
        const unsigned long long* p = (const unsigned long long*)edges;
        int is64 = 1;
        #pragma unroll
        for (int k = 0; k < 8; k++)
            if (p[k] >= (1ull << 32)) is64 = 0;
        d_is64 = is64;
    }
}

// ---------------------------------------------------------------------------
// Edge scatter: agg[dst[e]] += x[src[e]].  8 edges/thread.
// All 8 gathers issued (MLP=8) before the 8 REDs.
// edge_index layout: [2, E] row-major -> src = [0,E), dst = [E, 2E).
// ---------------------------------------------------------------------------
#define EDGES_PER_THREAD 8
__global__ void __launch_bounds__(256) edge_kernel(
        const void* __restrict__ edge_ptr,
        const float* __restrict__ x,
        long long n_edges) {
    long long t    = (long long)blockIdx.x * blockDim.x + threadIdx.x;
    long long base = t * EDGES_PER_THREAD;
    if (base >= n_edges) return;
    const int is64 = d_is64;

    int s[8], d[8];
    if (base + EDGES_PER_THREAD <= n_edges &&
        (n_edges & (EDGES_PER_THREAD - 1)) == 0) {
        // Fast path: aligned full batch
        if (is64) {
            const longlong2* src2 = (const longlong2*)edge_ptr;   // 2 idx / 16B
            const longlong2* dst2 = src2 + (n_edges >> 1);
            long long q = base >> 1;
            #pragma unroll
            for (int j = 0; j < 4; j++) {
                longlong2 a = __ldg(&src2[q + j]);
                s[2*j] = (int)a.x; s[2*j+1] = (int)a.y;
            }
            #pragma unroll
            for (int j = 0; j < 4; j++) {
                longlong2 a = __ldg(&dst2[q + j]);
                d[2*j] = (int)a.x; d[2*j+1] = (int)a.y;
            }
        } else {
            const int4* src4 = (const int4*)edge_ptr;             // 4 idx / 16B
            const int4* dst4 = (const int4*)((const int*)edge_ptr + n_edges);
            long long q = base >> 2;
            #pragma unroll
            for (int j = 0; j < 2; j++) {
                int4 a = __ldg(&src4[q + j]);
                s[4*j] = a.x; s[4*j+1] = a.y; s[4*j+2] = a.z; s[4*j+3] = a.w;
            }
            #pragma unroll
            for (int j = 0; j < 2; j++) {
                int4 a = __ldg(&dst4[q + j]);
                d[4*j] = a.x; d[4*j+1] = a.y; d[4*j+2] = a.z; d[4*j+3] = a.w;
            }
        }
        float v[8];
        #pragma unroll
        for (int k = 0; k < 8; k++) v[k] = __ldg(&x[s[k]]);
        #pragma unroll
        for (int k = 0; k < 8; k++) atomicAdd(&d_agg[d[k]], v[k]); // RED.E.ADD
    } else {
        // Tail path (generic)
        for (int k = 0; k < EDGES_PER_THREAD; k++) {
            long long e = base + k;
            if (e >= n_edges) break;
            int si, di;
            if (is64) {
                si = (int)((const long long*)edge_ptr)[e];
                di = (int)((const long long*)edge_ptr)[n_edges + e];
            } else {
                si = ((const int*)edge_ptr)[e];
                di = ((const int*)edge_ptr)[n_edges + e];
            }
            atomicAdd(&d_agg[di], __ldg(&x[si]));
        }
    }
}

// ---------------------------------------------------------------------------
// ReLU + segmented pool. batch is SORTED: each thread takes 4 contiguous
// nodes (vector loads), accumulates locally, flushes per-graph atomics only
// on graph-id change (~1-2 flushes/thread).
// ---------------------------------------------------------------------------
#define NODES_PER_THREAD 4
__global__ void __launch_bounds__(256) pool_kernel(const void* __restrict__ batch_ptr) {
    long long t    = (long long)blockIdx.x * blockDim.x + threadIdx.x;
    long long base = t * NODES_PER_THREAD;
    if (base >= N_NODES) return;
    const int is64 = d_is64;

    int g[4];
    float h[4];
    if (base + 4 <= N_NODES && (N_NODES % 4) == 0) {
        float4 a = *(const float4*)&d_agg[base];
        h[0] = a.x; h[1] = a.y; h[2] = a.z; h[3] = a.w;
        if (is64) {
            const longlong2* bp = (const longlong2*)batch_ptr;
            longlong2 b0 = __ldg(&bp[(base >> 1)]);
            longlong2 b1 = __ldg(&bp[(base >> 1) + 1]);
            g[0] = (int)b0.x; g[1] = (int)b0.y; g[2] = (int)b1.x; g[3] = (int)b1.y;
        } else {
            int4 b = __ldg(&((const int4*)batch_ptr)[base >> 2]);
            g[0] = b.x; g[1] = b.y; g[2] = b.z; g[3] = b.w;
        }
    } else {
        for (int k = 0; k < 4; k++) {
            long long i = base + k;
            if (i < N_NODES) {
                h[k] = d_agg[i];
                g[k] = is64 ? (int)((const long long*)batch_ptr)[i]
                            : ((const int*)batch_ptr)[i];
            } else { h[k] = 0.0f; g[k] = -1; }
        }
    }

    int cur = g[0];
    float s = 0.0f, c = 0.0f;
    #pragma unroll
    for (int k = 0; k < 4; k++) {
        if (g[k] < 0) break;
        float hv = h[k] > 0.0f ? h[k] : 0.0f;
        if (g[k] != cur) {
            atomicAdd(&d_gsum[cur], s);
            atomicAdd(&d_gcnt[cur], c);
            cur = g[k]; s = 0.0f; c = 0.0f;
        }
        s += hv; c += 1.0f;
    }
    if (cur >= 0) {
        atomicAdd(&d_gsum[cur], s);
        atomicAdd(&d_gcnt[cur], c);
    }
}

// ---------------------------------------------------------------------------
// out[g] = (gsum[g] / max(gcnt[g], 1)) * W[0,0] + b[0]
// ---------------------------------------------------------------------------
__global__ void out_kernel(const float* __restrict__ W,
                           const float* __restrict__ b,
                           float* __restrict__ out) {
    int g = blockIdx.x * blockDim.x + threadIdx.x;
    if (g < NUM_GRAPHS) {
        float cnt = fmaxf(d_gcnt[g], 1.0f);
        out[g] = (d_gsum[g] / cnt) * W[0] + b[0];
    }
}

extern "C" void kernel_launch(void* const* d_in, const int* in_sizes, int n_in,
                              void* d_out, int out_size) {
    const float* x     = (const float*)d_in[0];
    const float* W     = (const float*)d_in[1];
    const float* b     = (const float*)d_in[2];
    const void*  edges = d_in[3];
    const void*  batch = d_in[4];
    long long n_edges  = (long long)in_sizes[3] / 2;   // [2, E] -> E

    // 4 launches per call: init, edge, pool, out.
    // (ncu -s 5 then profiles replay #2's edge_kernel — the dominant one.)
    init_kernel<<<(N_NODES + 255) / 256, 256>>>(edges);

    long long edge_threads = (n_edges + EDGES_PER_THREAD - 1) / EDGES_PER_THREAD;
    edge_kernel<<<(int)((edge_threads + 255) / 256), 256>>>(edges, x, n_edges);

    long long pool_threads = (N_NODES + NODES_PER_THREAD - 1) / NODES_PER_THREAD;
    pool_kernel<<<(int)((pool_threads + 255) / 256), 256>>>(batch);

    out_kernel<<<(NUM_GRAPHS + 255) / 256, 256>>>(W, b, (float*)d_out);
}

// round 7
// speedup vs baseline: 1.0748x; 1.0748x over previous
#include <cuda_runtime.h>
#include <cuda_bf16.h>

#define N_NODES    1000000
#define NUM_GRAPHS 1024

// Scratch (device globals: no allocations allowed)
__device__ float d_agg[N_NODES];      // per-node aggregated sum
__device__ float d_gsum[NUM_GRAPHS];  // per-graph sum of relu(agg)
__device__ float d_gcnt[NUM_GRAPHS];  // per-graph node count
__device__ int   d_is64;              // 1 if indices are int64, 0 if int32
__device__ unsigned int d_pool_done;  // completion counter for fused output

// ---------------------------------------------------------------------------
// Init: zero scratch + detect index dtype (thread 0).
// JAX with x64 disabled silently downcasts int64->int32: an int32 pair
// reinterpreted as int64 is >= 2^32 w.p. ~1; true int64 indices are < 1e6.
// ---------------------------------------------------------------------------
__global__ void init_kernel(const void* __restrict__ edges) {
    int i = blockIdx.x * blockDim.x + threadIdx.x;
    if (i < N_NODES) d_agg[i] = 0.0f;
    if (i < NUM_GRAPHS) { d_gsum[i] = 0.0f; d_gcnt[i] = 0.0f; }
    if (i == 0) {
        const unsigned long long* p = (const unsigned long long*)edges;
        int is64 = 1;
        #pragma unroll
        for (int k = 0; k < 8; k++)
            if (p[k] >= (1ull << 32)) is64 = 0;
        d_is64 = is64;
        d_pool_done = 0;
    }
}

// ---------------------------------------------------------------------------
// Edge scatter: agg[dst[e]] += x[src[e]].  4 edges/thread (R2 winning shape).
// Index stream loaded with .cs (evict-first): 512MB one-pass data must not
// evict the L2-resident x / d_agg (8MB) gather working set.
// edge_index layout: [2, E] row-major -> src = [0,E), dst = [E, 2E).
// ---------------------------------------------------------------------------
__global__ void __launch_bounds__(256) edge_kernel(
        const void* __restrict__ edge_ptr,
        const float* __restrict__ x,
        long long n_edges) {
    long long t    = (long long)blockIdx.x * blockDim.x + threadIdx.x;
    long long base = t * 4;
    if (base >= n_edges) return;

    int s[4], d[4];
    if (d_is64) {
        const longlong2* src2 = (const longlong2*)edge_ptr;          // 2 idx / 16B
        const longlong2* dst2 = src2 + (n_edges >> 1);
        longlong2 a = __ldcs(&src2[base >> 1]);
        longlong2 b = __ldcs(&src2[(base >> 1) + 1]);
        longlong2 c = __ldcs(&dst2[base >> 1]);
        longlong2 e = __ldcs(&dst2[(base >> 1) + 1]);
        s[0] = (int)a.x; s[1] = (int)a.y; s[2] = (int)b.x; s[3] = (int)b.y;
        d[0] = (int)c.x; d[1] = (int)c.y; d[2] = (int)e.x; d[3] = (int)e.y;
    } else {
        const int4* src4 = (const int4*)edge_ptr;                    // 4 idx / 16B
        const int4* dst4 = (const int4*)((const int*)edge_ptr + n_edges);
        int4 a = __ldcs(&src4[base >> 2]);
        int4 c = __ldcs(&dst4[base >> 2]);
        s[0] = a.x; s[1] = a.y; s[2] = a.z; s[3] = a.w;
        d[0] = c.x; d[1] = c.y; d[2] = c.z; d[3] = c.w;
    }

    #pragma unroll
    for (int k = 0; k < 4; k++) {
        if (base + k < n_edges) {
            float xv = __ldg(&x[s[k]]);
            atomicAdd(&d_agg[d[k]], xv);   // result unused -> RED.E.ADD.F32
        }
    }
}

// ---------------------------------------------------------------------------
// ReLU + segmented pool + FUSED output. batch is SORTED: each thread takes 8
// contiguous nodes (float4-vectorized), accumulates locally, flushes
// per-graph atomics only on graph-id change. The LAST block to finish
// (completion counter) computes out[g] = mean * W + b for all 1024 graphs.
// ---------------------------------------------------------------------------
#define NODES_PER_THREAD 8
__global__ void __launch_bounds__(256) pool_kernel(
        const void* __restrict__ batch_ptr,
        const float* __restrict__ W,
        const float* __restrict__ b,
        float* __restrict__ out) {
    long long t    = (long long)blockIdx.x * blockDim.x + threadIdx.x;
    long long base = t * NODES_PER_THREAD;
    const int is64 = d_is64;

    if (base < N_NODES) {
        int   g[NODES_PER_THREAD];
        float h[NODES_PER_THREAD];
        if (base + NODES_PER_THREAD <= N_NODES) {
            #pragma unroll
            for (int j = 0; j < NODES_PER_THREAD / 4; j++) {
                float4 a = *(const float4*)&d_agg[base + 4*j];
                h[4*j] = a.x; h[4*j+1] = a.y; h[4*j+2] = a.z; h[4*j+3] = a.w;
            }
            if (is64) {
                const longlong2* bp = (const longlong2*)batch_ptr;
                #pragma unroll
                for (int j = 0; j < NODES_PER_THREAD / 2; j++) {
                    longlong2 v = __ldg(&bp[(base >> 1) + j]);
                    g[2*j] = (int)v.x; g[2*j+1] = (int)v.y;
                }
            } else {
                const int4* bp = (const int4*)batch_ptr;
                #pragma unroll
                for (int j = 0; j < NODES_PER_THREAD / 4; j++) {
                    int4 v = __ldg(&bp[(base >> 2) + j]);
                    g[4*j] = v.x; g[4*j+1] = v.y; g[4*j+2] = v.z; g[4*j+3] = v.w;
                }
            }
        } else {
            for (int k = 0; k < NODES_PER_THREAD; k++) {
                long long i = base + k;
                if (i < N_NODES) {
                    h[k] = d_agg[i];
                    g[k] = is64 ? (int)((const long long*)batch_ptr)[i]
                                : ((const int*)batch_ptr)[i];
                } else { h[k] = 0.0f; g[k] = -1; }
            }
        }

        int cur = g[0];
        float s = 0.0f, c = 0.0f;
        #pragma unroll
        for (int k = 0; k < NODES_PER_THREAD; k++) {
            if (g[k] < 0) break;
            float hv = h[k] > 0.0f ? h[k] : 0.0f;
            if (g[k] != cur) {
                atomicAdd(&d_gsum[cur], s);
                atomicAdd(&d_gcnt[cur], c);
                cur = g[k]; s = 0.0f; c = 0.0f;
            }
            s += hv; c += 1.0f;
        }
        if (cur >= 0) {
            atomicAdd(&d_gsum[cur], s);
            atomicAdd(&d_gcnt[cur], c);
        }
    }

    // ---- fused output: last block to finish computes out[0..1023] ----
    __threadfence();                       // make REDs above visible
    __syncthreads();
    __shared__ int s_last;
    if (threadIdx.x == 0) {
        unsigned int prev = atomicAdd(&d_pool_done, 1u);
        s_last = (prev == gridDim.x - 1) ? 1 : 0;
    }
    __syncthreads();
    if (s_last) {
        float Wv = __ldg(&W[0]);
        float bv = __ldg(&b[0]);
        for (int g2 = threadIdx.x; g2 < NUM_GRAPHS; g2 += blockDim.x) {
            float cnt = fmaxf(d_gcnt[g2], 1.0f);
            out[g2] = (d_gsum[g2] / cnt) * Wv + bv;
        }
    }
}

extern "C" void kernel_launch(void* const* d_in, const int* in_sizes, int n_in,
                              void* d_out, int out_size) {
    const float* x     = (const float*)d_in[0];
    const float* W     = (const float*)d_in[1];
    const float* b     = (const float*)d_in[2];
    const void*  edges = d_in[3];
    const void*  batch = d_in[4];
    long long n_edges  = (long long)in_sizes[3] / 2;   // [2, E] -> E

    init_kernel<<<(N_NODES + 255) / 256, 256>>>(edges);

    long long edge_threads = (n_edges + 3) / 4;
    edge_kernel<<<(int)((edge_threads + 255) / 256), 256>>>(edges, x, n_edges);

    long long pool_threads = (N_NODES + NODES_PER_THREAD - 1) / NODES_PER_THREAD;
    pool_kernel<<<(int)((pool_threads + 255) / 256), 256>>>(batch, W, b,
                                                            (float*)d_out);
}